// round 9
// baseline (speedup 1.0000x reference)
#include <cuda_runtime.h>

#define BB 4
#define NN 50000
#define DD 256
#define EE 800000
#define TAU_MIN_F 0.001f
#define MAX_CORR_F 0.15f
#define XPBD_ITERS_I 4

// Node-major packed positions: x[buf][node][batch][xyz]
// 12 floats (48 B) per node, no padding. 2 * 2.4 MB = 4.8 MB (L2-resident).
#define XN (NN * 12)
__device__ __align__(16) float g_x[2][XN];

// ---------------------------------------------------------------------------
// Kernel 1: x_pred = keypoints + tau * (hand_tokens @ head_w + head_b)
// warp-per-(b,node) row; writes BOTH ping-pong buffers (pre-copies iter 0).
// ---------------------------------------------------------------------------
__global__ void pred_kernel(const float* __restrict__ keypoints,
                            const float* __restrict__ timesteps,
                            const float* __restrict__ hand_tokens,
                            const float* __restrict__ head_w,
                            const float* __restrict__ head_b) {
    __shared__ float sw[DD * 3];
    int tid = threadIdx.x;
    for (int i = tid; i < DD * 3; i += blockDim.x) sw[i] = head_w[i];
    __syncthreads();

    int row = (int)((blockIdx.x * (size_t)blockDim.x + tid) >> 5);
    int lane = tid & 31;
    if (row >= BB * NN) return;

    const float4* hrow =
        reinterpret_cast<const float4*>(hand_tokens + (size_t)row * DD);
    float4 a = hrow[lane];
    float4 c = hrow[lane + 32];

    float acc0 = 0.f, acc1 = 0.f, acc2 = 0.f;
    int d0 = lane * 4;
    {
        const float* w = &sw[d0 * 3];
        acc0 += a.x * w[0] + a.y * w[3] + a.z * w[6] + a.w * w[9];
        acc1 += a.x * w[1] + a.y * w[4] + a.z * w[7] + a.w * w[10];
        acc2 += a.x * w[2] + a.y * w[5] + a.z * w[8] + a.w * w[11];
    }
    {
        const float* w = &sw[(d0 + 128) * 3];
        acc0 += c.x * w[0] + c.y * w[3] + c.z * w[6] + c.w * w[9];
        acc1 += c.x * w[1] + c.y * w[4] + c.z * w[7] + c.w * w[10];
        acc2 += c.x * w[2] + c.y * w[5] + c.z * w[8] + c.w * w[11];
    }

#pragma unroll
    for (int off = 16; off > 0; off >>= 1) {
        acc0 += __shfl_xor_sync(0xFFFFFFFFu, acc0, off);
        acc1 += __shfl_xor_sync(0xFFFFFFFFu, acc1, off);
        acc2 += __shfl_xor_sync(0xFFFFFFFFu, acc2, off);
    }

    if (lane == 0) {
        int b = row / NN;
        int node = row - b * NN;
        float tau = fmaxf(1.0f - timesteps[b], TAU_MIN_F);
        size_t o = 3 * (size_t)row;
        float px = keypoints[o + 0] + tau * (acc0 + head_b[0]);
        float py = keypoints[o + 1] + tau * (acc1 + head_b[1]);
        float pz = keypoints[o + 2] + tau * (acc2 + head_b[2]);
        int base = node * 12 + b * 3;
        g_x[0][base + 0] = px;
        g_x[0][base + 1] = py;
        g_x[0][base + 2] = pz;
        g_x[1][base + 0] = px;  // pre-copy for iteration 0's scatter target
        g_x[1][base + 1] = py;
        g_x[1][base + 2] = pz;
    }
}

// ---------------------------------------------------------------------------
// Kernel 2: one XPBD Jacobi iteration, 1 edge/thread (R7 floor config).
// Position loads bypass L1 (.cg) — L1D is flushed per launch so there is
// zero cross-launch reuse; this trims L1tex wavefront pressure.
// ---------------------------------------------------------------------------
__device__ __forceinline__ float4 ldcg_f4(const float4* p) {
    float4 v;
    asm volatile("ld.global.cg.v4.f32 {%0, %1, %2, %3}, [%4];"
                 : "=f"(v.x), "=f"(v.y), "=f"(v.z), "=f"(v.w)
                 : "l"(p));
    return v;
}

__device__ __forceinline__ void red_add_v4(const float* ptr, float a, float b,
                                           float c, float d) {
    asm volatile("red.global.add.v4.f32 [%0], {%1, %2, %3, %4};"
                 :: "l"(ptr), "f"(a), "f"(b), "f"(c), "f"(d)
                 : "memory");
}

__global__ void __launch_bounds__(256) edge_kernel(
    const int* __restrict__ edge_index, const float* __restrict__ rest,
    int cur, int nxt) {
    int e = blockIdx.x * blockDim.x + threadIdx.x;
    if (e >= EE) return;
    int s = edge_index[e];
    int d = edge_index[EE + e];
    float L0 = rest[e];

    const float4* S4 = reinterpret_cast<const float4*>(&g_x[cur][s * 12]);
    const float4* D4 = reinterpret_cast<const float4*>(&g_x[cur][d * 12]);
    float S[12], D[12], C[12];
#pragma unroll
    for (int k = 0; k < 3; k++) {
        reinterpret_cast<float4*>(S)[k] = ldcg_f4(&S4[k]);
        reinterpret_cast<float4*>(D)[k] = ldcg_f4(&D4[k]);
    }

#pragma unroll
    for (int b = 0; b < BB; b++) {
        float dx = S[b * 3 + 0] - D[b * 3 + 0];
        float dy = S[b * 3 + 1] - D[b * 3 + 1];
        float dz = S[b * 3 + 2] - D[b * 3 + 2];
        float d2 = fmaf(dx, dx, fmaf(dy, dy, dz * dz)) + 1e-24f;
        float rinv = rsqrtf(d2);
        float dist = d2 * rinv;
        float f = (L0 - dist) * 0.5f * rinv;
        C[b * 3 + 0] = fminf(fmaxf(f * dx, -MAX_CORR_F), MAX_CORR_F);
        C[b * 3 + 1] = fminf(fmaxf(f * dy, -MAX_CORR_F), MAX_CORR_F);
        C[b * 3 + 2] = fminf(fmaxf(f * dz, -MAX_CORR_F), MAX_CORR_F);
    }

    const float* outS = &g_x[nxt][s * 12];
    const float* outD = &g_x[nxt][d * 12];
    red_add_v4(outS + 0, C[0], C[1], C[2], C[3]);
    red_add_v4(outS + 4, C[4], C[5], C[6], C[7]);
    red_add_v4(outS + 8, C[8], C[9], C[10], C[11]);
    red_add_v4(outD + 0, -C[0], -C[1], -C[2], -C[3]);
    red_add_v4(outD + 4, -C[4], -C[5], -C[6], -C[7]);
    red_add_v4(outD + 8, -C[8], -C[9], -C[10], -C[11]);
}

// ---------------------------------------------------------------------------
// Kernel 3: v_eff = (x_corrected - keypoints) / tau
// ---------------------------------------------------------------------------
__global__ void final_kernel(const float* __restrict__ keypoints,
                             const float* __restrict__ timesteps,
                             float* __restrict__ out, int cur) {
    int i = blockIdx.x * blockDim.x + threadIdx.x;
    if (i >= BB * NN) return;
    int b = i / NN;
    int node = i - b * NN;
    float tau = fmaxf(1.0f - timesteps[b], TAU_MIN_F);
    int base = node * 12 + b * 3;
    size_t o = 3 * (size_t)i;
    out[o + 0] = (g_x[cur][base + 0] - keypoints[o + 0]) / tau;
    out[o + 1] = (g_x[cur][base + 1] - keypoints[o + 1]) / tau;
    out[o + 2] = (g_x[cur][base + 2] - keypoints[o + 2]) / tau;
}

extern "C" void kernel_launch(void* const* d_in, const int* in_sizes, int n_in,
                              void* d_out, int out_size) {
    const float* keypoints = (const float*)d_in[0];
    const float* timesteps = (const float*)d_in[1];
    const float* hand_tokens = (const float*)d_in[2];
    const float* head_w = (const float*)d_in[3];
    const float* head_b = (const float*)d_in[4];
    const int* edge_index = (const int*)d_in[5];
    const float* rest = (const float*)d_in[6];
    float* out = (float*)d_out;

    const int rows = BB * NN;  // 200000

    float* x_base = nullptr;
    cudaGetSymbolAddress((void**)&x_base, g_x);

    // Phase 1: prediction head (writes both ping-pong buffers)
    {
        long long threads = (long long)rows * 32;
        pred_kernel<<<(int)((threads + 255) / 256), 256>>>(
            keypoints, timesteps, hand_tokens, head_w, head_b);
    }

    // Phase 2: XPBD Jacobi iterations (scatter with packed v4 REDs)
    int cur = 0;
    for (int it = 0; it < XPBD_ITERS_I; it++) {
        int nxt = cur ^ 1;
        if (it > 0) {
            cudaMemcpyAsync(x_base + (size_t)nxt * XN,
                            x_base + (size_t)cur * XN, XN * sizeof(float),
                            cudaMemcpyDeviceToDevice);
        }
        edge_kernel<<<(EE + 255) / 256, 256>>>(edge_index, rest, cur, nxt);
        cur = nxt;
    }

    // Phase 3: effective velocity
    final_kernel<<<(rows + 255) / 256, 256>>>(keypoints, timesteps, out, cur);
}

// round 10
// speedup vs baseline: 1.0964x; 1.0964x over previous
#include <cuda_runtime.h>

#define BB 4
#define NN 50000
#define DD 256
#define EE 800000
#define TAU_MIN_F 0.001f
#define MAX_CORR_F 0.15f
#define XPBD_ITERS_I 4

// Node-major packed positions: x[buf][node][batch][xyz]
// 12 floats (48 B) per node, no padding. 2 * 2.4 MB = 4.8 MB (L2-resident).
#define XN (NN * 12)
__device__ __align__(16) float g_x[2][XN];

// ---------------------------------------------------------------------------
// Kernel 1: x_pred = keypoints + tau * (hand_tokens @ head_w + head_b)
// warp-per-(b,node) row; writes BOTH ping-pong buffers (pre-copies iter 0).
// hand_tokens is single-use -> evict-first streaming loads (__ldcs).
// ---------------------------------------------------------------------------
__global__ void pred_kernel(const float* __restrict__ keypoints,
                            const float* __restrict__ timesteps,
                            const float* __restrict__ hand_tokens,
                            const float* __restrict__ head_w,
                            const float* __restrict__ head_b) {
    __shared__ float sw[DD * 3];
    int tid = threadIdx.x;
    for (int i = tid; i < DD * 3; i += blockDim.x) sw[i] = head_w[i];
    __syncthreads();

    int row = (int)((blockIdx.x * (size_t)blockDim.x + tid) >> 5);
    int lane = tid & 31;
    if (row >= BB * NN) return;

    const float4* hrow =
        reinterpret_cast<const float4*>(hand_tokens + (size_t)row * DD);
    float4 a = __ldcs(&hrow[lane]);
    float4 c = __ldcs(&hrow[lane + 32]);

    float acc0 = 0.f, acc1 = 0.f, acc2 = 0.f;
    int d0 = lane * 4;
    {
        const float* w = &sw[d0 * 3];
        acc0 += a.x * w[0] + a.y * w[3] + a.z * w[6] + a.w * w[9];
        acc1 += a.x * w[1] + a.y * w[4] + a.z * w[7] + a.w * w[10];
        acc2 += a.x * w[2] + a.y * w[5] + a.z * w[8] + a.w * w[11];
    }
    {
        const float* w = &sw[(d0 + 128) * 3];
        acc0 += c.x * w[0] + c.y * w[3] + c.z * w[6] + c.w * w[9];
        acc1 += c.x * w[1] + c.y * w[4] + c.z * w[7] + c.w * w[10];
        acc2 += c.x * w[2] + c.y * w[5] + c.z * w[8] + c.w * w[11];
    }

#pragma unroll
    for (int off = 16; off > 0; off >>= 1) {
        acc0 += __shfl_xor_sync(0xFFFFFFFFu, acc0, off);
        acc1 += __shfl_xor_sync(0xFFFFFFFFu, acc1, off);
        acc2 += __shfl_xor_sync(0xFFFFFFFFu, acc2, off);
    }

    if (lane == 0) {
        int b = row / NN;
        int node = row - b * NN;
        float tau = fmaxf(1.0f - timesteps[b], TAU_MIN_F);
        size_t o = 3 * (size_t)row;
        float px = keypoints[o + 0] + tau * (acc0 + head_b[0]);
        float py = keypoints[o + 1] + tau * (acc1 + head_b[1]);
        float pz = keypoints[o + 2] + tau * (acc2 + head_b[2]);
        int base = node * 12 + b * 3;
        g_x[0][base + 0] = px;
        g_x[0][base + 1] = py;
        g_x[0][base + 2] = pz;
        g_x[1][base + 0] = px;  // pre-copy for iteration 0's scatter target
        g_x[1][base + 1] = py;
        g_x[1][base + 2] = pz;
    }
}

// ---------------------------------------------------------------------------
// Kernel 2: one XPBD Jacobi iteration, 1 edge/thread (R7 floor config).
// Plain (L1-cached) loads: avg node degree 32 gives strong intra-launch L1
// reuse of position data. Scatter via 3 fully-packed v4 REDs per endpoint.
// ---------------------------------------------------------------------------
__device__ __forceinline__ void red_add_v4(const float* ptr, float a, float b,
                                           float c, float d) {
    asm volatile("red.global.add.v4.f32 [%0], {%1, %2, %3, %4};"
                 :: "l"(ptr), "f"(a), "f"(b), "f"(c), "f"(d)
                 : "memory");
}

__global__ void __launch_bounds__(256) edge_kernel(
    const int* __restrict__ edge_index, const float* __restrict__ rest,
    int cur, int nxt) {
    int e = blockIdx.x * blockDim.x + threadIdx.x;
    if (e >= EE) return;
    int s = edge_index[e];
    int d = edge_index[EE + e];
    float L0 = rest[e];

    const float4* S4 = reinterpret_cast<const float4*>(&g_x[cur][s * 12]);
    const float4* D4 = reinterpret_cast<const float4*>(&g_x[cur][d * 12]);
    float S[12], D[12], C[12];
#pragma unroll
    for (int k = 0; k < 3; k++) {
        reinterpret_cast<float4*>(S)[k] = S4[k];
        reinterpret_cast<float4*>(D)[k] = D4[k];
    }

#pragma unroll
    for (int b = 0; b < BB; b++) {
        float dx = S[b * 3 + 0] - D[b * 3 + 0];
        float dy = S[b * 3 + 1] - D[b * 3 + 1];
        float dz = S[b * 3 + 2] - D[b * 3 + 2];
        float d2 = fmaf(dx, dx, fmaf(dy, dy, dz * dz)) + 1e-24f;
        float rinv = rsqrtf(d2);
        float dist = d2 * rinv;
        float f = (L0 - dist) * 0.5f * rinv;
        C[b * 3 + 0] = fminf(fmaxf(f * dx, -MAX_CORR_F), MAX_CORR_F);
        C[b * 3 + 1] = fminf(fmaxf(f * dy, -MAX_CORR_F), MAX_CORR_F);
        C[b * 3 + 2] = fminf(fmaxf(f * dz, -MAX_CORR_F), MAX_CORR_F);
    }

    const float* outS = &g_x[nxt][s * 12];
    const float* outD = &g_x[nxt][d * 12];
    red_add_v4(outS + 0, C[0], C[1], C[2], C[3]);
    red_add_v4(outS + 4, C[4], C[5], C[6], C[7]);
    red_add_v4(outS + 8, C[8], C[9], C[10], C[11]);
    red_add_v4(outD + 0, -C[0], -C[1], -C[2], -C[3]);
    red_add_v4(outD + 4, -C[4], -C[5], -C[6], -C[7]);
    red_add_v4(outD + 8, -C[8], -C[9], -C[10], -C[11]);
}

// ---------------------------------------------------------------------------
// Kernel 3: v_eff = (x_corrected - keypoints) / tau
// ---------------------------------------------------------------------------
__global__ void final_kernel(const float* __restrict__ keypoints,
                             const float* __restrict__ timesteps,
                             float* __restrict__ out, int cur) {
    int i = blockIdx.x * blockDim.x + threadIdx.x;
    if (i >= BB * NN) return;
    int b = i / NN;
    int node = i - b * NN;
    float tau = fmaxf(1.0f - timesteps[b], TAU_MIN_F);
    int base = node * 12 + b * 3;
    size_t o = 3 * (size_t)i;
    out[o + 0] = (g_x[cur][base + 0] - keypoints[o + 0]) / tau;
    out[o + 1] = (g_x[cur][base + 1] - keypoints[o + 1]) / tau;
    out[o + 2] = (g_x[cur][base + 2] - keypoints[o + 2]) / tau;
}

extern "C" void kernel_launch(void* const* d_in, const int* in_sizes, int n_in,
                              void* d_out, int out_size) {
    const float* keypoints = (const float*)d_in[0];
    const float* timesteps = (const float*)d_in[1];
    const float* hand_tokens = (const float*)d_in[2];
    const float* head_w = (const float*)d_in[3];
    const float* head_b = (const float*)d_in[4];
    const int* edge_index = (const int*)d_in[5];
    const float* rest = (const float*)d_in[6];
    float* out = (float*)d_out;

    const int rows = BB * NN;  // 200000

    float* x_base = nullptr;
    cudaGetSymbolAddress((void**)&x_base, g_x);

    // Phase 1: prediction head (writes both ping-pong buffers)
    {
        long long threads = (long long)rows * 32;
        pred_kernel<<<(int)((threads + 255) / 256), 256>>>(
            keypoints, timesteps, hand_tokens, head_w, head_b);
    }

    // Phase 2: XPBD Jacobi iterations (scatter with packed v4 REDs)
    int cur = 0;
    for (int it = 0; it < XPBD_ITERS_I; it++) {
        int nxt = cur ^ 1;
        if (it > 0) {
            cudaMemcpyAsync(x_base + (size_t)nxt * XN,
                            x_base + (size_t)cur * XN, XN * sizeof(float),
                            cudaMemcpyDeviceToDevice);
        }
        edge_kernel<<<(EE + 255) / 256, 256>>>(edge_index, rest, cur, nxt);
        cur = nxt;
    }

    // Phase 3: effective velocity
    final_kernel<<<(rows + 255) / 256, 256>>>(keypoints, timesteps, out, cur);
}

// round 11
// speedup vs baseline: 1.1927x; 1.0878x over previous
#include <cuda_runtime.h>

#define BB 4
#define NN 50000
#define DD 256
#define EE 800000
#define TAU_MIN_F 0.001f
#define MAX_CORR_F 0.15f
#define XPBD_ITERS_I 4

// Node-major packed positions: x[buf][node][batch][xyz]
// 12 floats (48 B) per node, no padding. 2 * 2.4 MB = 4.8 MB (L2-resident).
#define XN (NN * 12)
__device__ __align__(16) float g_x[2][XN];

// ---------------------------------------------------------------------------
// Kernel 1: x_pred = keypoints + tau * (hand_tokens @ head_w + head_b)
// TWO rows per warp -> 4 independent LDG.128 per lane (MLP=4) to ride the
// DRAM latency harder. Butterfly reduce leaves sums in all lanes; lane 0
// writes row0, lane 1 writes row1. Writes BOTH ping-pong buffers.
// ---------------------------------------------------------------------------
__global__ void pred_kernel(const float* __restrict__ keypoints,
                            const float* __restrict__ timesteps,
                            const float* __restrict__ hand_tokens,
                            const float* __restrict__ head_w,
                            const float* __restrict__ head_b) {
    __shared__ float sw[DD * 3];
    int tid = threadIdx.x;
    for (int i = tid; i < DD * 3; i += blockDim.x) sw[i] = head_w[i];
    __syncthreads();

    int warp = (int)((blockIdx.x * (size_t)blockDim.x + tid) >> 5);
    int lane = tid & 31;
    int r0 = warp * 2;
    if (r0 >= BB * NN) return;
    int r1 = r0 + 1;

    const float4* h0 =
        reinterpret_cast<const float4*>(hand_tokens + (size_t)r0 * DD);
    const float4* h1 =
        reinterpret_cast<const float4*>(hand_tokens + (size_t)r1 * DD);
    // 4 independent streaming loads batched up front.
    float4 a0 = __ldcs(&h0[lane]);
    float4 c0 = __ldcs(&h0[lane + 32]);
    float4 a1 = __ldcs(&h1[lane]);
    float4 c1 = __ldcs(&h1[lane + 32]);

    float p0 = 0.f, p1 = 0.f, p2 = 0.f;  // row0 accumulators
    float q0 = 0.f, q1 = 0.f, q2 = 0.f;  // row1 accumulators
    int d0 = lane * 4;
    {
        const float* w = &sw[d0 * 3];
        p0 += a0.x * w[0] + a0.y * w[3] + a0.z * w[6] + a0.w * w[9];
        p1 += a0.x * w[1] + a0.y * w[4] + a0.z * w[7] + a0.w * w[10];
        p2 += a0.x * w[2] + a0.y * w[5] + a0.z * w[8] + a0.w * w[11];
        q0 += a1.x * w[0] + a1.y * w[3] + a1.z * w[6] + a1.w * w[9];
        q1 += a1.x * w[1] + a1.y * w[4] + a1.z * w[7] + a1.w * w[10];
        q2 += a1.x * w[2] + a1.y * w[5] + a1.z * w[8] + a1.w * w[11];
    }
    {
        const float* w = &sw[(d0 + 128) * 3];
        p0 += c0.x * w[0] + c0.y * w[3] + c0.z * w[6] + c0.w * w[9];
        p1 += c0.x * w[1] + c0.y * w[4] + c0.z * w[7] + c0.w * w[10];
        p2 += c0.x * w[2] + c0.y * w[5] + c0.z * w[8] + c0.w * w[11];
        q0 += c1.x * w[0] + c1.y * w[3] + c1.z * w[6] + c1.w * w[9];
        q1 += c1.x * w[1] + c1.y * w[4] + c1.z * w[7] + c1.w * w[10];
        q2 += c1.x * w[2] + c1.y * w[5] + c1.z * w[8] + c1.w * w[11];
    }

#pragma unroll
    for (int off = 16; off > 0; off >>= 1) {
        p0 += __shfl_xor_sync(0xFFFFFFFFu, p0, off);
        p1 += __shfl_xor_sync(0xFFFFFFFFu, p1, off);
        p2 += __shfl_xor_sync(0xFFFFFFFFu, p2, off);
        q0 += __shfl_xor_sync(0xFFFFFFFFu, q0, off);
        q1 += __shfl_xor_sync(0xFFFFFFFFu, q1, off);
        q2 += __shfl_xor_sync(0xFFFFFFFFu, q2, off);
    }

    if (lane < 2) {
        int row = (lane == 0) ? r0 : r1;
        float acc0 = (lane == 0) ? p0 : q0;
        float acc1 = (lane == 0) ? p1 : q1;
        float acc2 = (lane == 0) ? p2 : q2;
        int b = row / NN;
        int node = row - b * NN;
        float tau = fmaxf(1.0f - timesteps[b], TAU_MIN_F);
        size_t o = 3 * (size_t)row;
        float px = keypoints[o + 0] + tau * (acc0 + head_b[0]);
        float py = keypoints[o + 1] + tau * (acc1 + head_b[1]);
        float pz = keypoints[o + 2] + tau * (acc2 + head_b[2]);
        int base = node * 12 + b * 3;
        g_x[0][base + 0] = px;
        g_x[0][base + 1] = py;
        g_x[0][base + 2] = pz;
        g_x[1][base + 0] = px;  // pre-copy for iteration 0's scatter target
        g_x[1][base + 1] = py;
        g_x[1][base + 2] = pz;
    }
}

// ---------------------------------------------------------------------------
// Kernel 2: one XPBD Jacobi iteration, 1 edge/thread (R10 floor config —
// UNCHANGED). Plain L1-cached loads (avg degree 32 -> strong intra-launch
// reuse); scatter via 3 fully-packed v4 REDs per endpoint.
// ---------------------------------------------------------------------------
__device__ __forceinline__ void red_add_v4(const float* ptr, float a, float b,
                                           float c, float d) {
    asm volatile("red.global.add.v4.f32 [%0], {%1, %2, %3, %4};"
                 :: "l"(ptr), "f"(a), "f"(b), "f"(c), "f"(d)
                 : "memory");
}

__global__ void __launch_bounds__(256) edge_kernel(
    const int* __restrict__ edge_index, const float* __restrict__ rest,
    int cur, int nxt) {
    int e = blockIdx.x * blockDim.x + threadIdx.x;
    if (e >= EE) return;
    int s = edge_index[e];
    int d = edge_index[EE + e];
    float L0 = rest[e];

    const float4* S4 = reinterpret_cast<const float4*>(&g_x[cur][s * 12]);
    const float4* D4 = reinterpret_cast<const float4*>(&g_x[cur][d * 12]);
    float S[12], D[12], C[12];
#pragma unroll
    for (int k = 0; k < 3; k++) {
        reinterpret_cast<float4*>(S)[k] = S4[k];
        reinterpret_cast<float4*>(D)[k] = D4[k];
    }

#pragma unroll
    for (int b = 0; b < BB; b++) {
        float dx = S[b * 3 + 0] - D[b * 3 + 0];
        float dy = S[b * 3 + 1] - D[b * 3 + 1];
        float dz = S[b * 3 + 2] - D[b * 3 + 2];
        float d2 = fmaf(dx, dx, fmaf(dy, dy, dz * dz)) + 1e-24f;
        float rinv = rsqrtf(d2);
        float dist = d2 * rinv;
        float f = (L0 - dist) * 0.5f * rinv;
        C[b * 3 + 0] = fminf(fmaxf(f * dx, -MAX_CORR_F), MAX_CORR_F);
        C[b * 3 + 1] = fminf(fmaxf(f * dy, -MAX_CORR_F), MAX_CORR_F);
        C[b * 3 + 2] = fminf(fmaxf(f * dz, -MAX_CORR_F), MAX_CORR_F);
    }

    const float* outS = &g_x[nxt][s * 12];
    const float* outD = &g_x[nxt][d * 12];
    red_add_v4(outS + 0, C[0], C[1], C[2], C[3]);
    red_add_v4(outS + 4, C[4], C[5], C[6], C[7]);
    red_add_v4(outS + 8, C[8], C[9], C[10], C[11]);
    red_add_v4(outD + 0, -C[0], -C[1], -C[2], -C[3]);
    red_add_v4(outD + 4, -C[4], -C[5], -C[6], -C[7]);
    red_add_v4(outD + 8, -C[8], -C[9], -C[10], -C[11]);
}

// ---------------------------------------------------------------------------
// Kernel 3: v_eff = (x_corrected - keypoints) / tau
// ---------------------------------------------------------------------------
__global__ void final_kernel(const float* __restrict__ keypoints,
                             const float* __restrict__ timesteps,
                             float* __restrict__ out, int cur) {
    int i = blockIdx.x * blockDim.x + threadIdx.x;
    if (i >= BB * NN) return;
    int b = i / NN;
    int node = i - b * NN;
    float tau = fmaxf(1.0f - timesteps[b], TAU_MIN_F);
    int base = node * 12 + b * 3;
    size_t o = 3 * (size_t)i;
    out[o + 0] = (g_x[cur][base + 0] - keypoints[o + 0]) / tau;
    out[o + 1] = (g_x[cur][base + 1] - keypoints[o + 1]) / tau;
    out[o + 2] = (g_x[cur][base + 2] - keypoints[o + 2]) / tau;
}

extern "C" void kernel_launch(void* const* d_in, const int* in_sizes, int n_in,
                              void* d_out, int out_size) {
    const float* keypoints = (const float*)d_in[0];
    const float* timesteps = (const float*)d_in[1];
    const float* hand_tokens = (const float*)d_in[2];
    const float* head_w = (const float*)d_in[3];
    const float* head_b = (const float*)d_in[4];
    const int* edge_index = (const int*)d_in[5];
    const float* rest = (const float*)d_in[6];
    float* out = (float*)d_out;

    const int rows = BB * NN;  // 200000

    float* x_base = nullptr;
    cudaGetSymbolAddress((void**)&x_base, g_x);

    // Phase 1: prediction head (2 rows/warp; writes both ping-pong buffers)
    {
        long long threads = (long long)(rows / 2) * 32;  // rows even
        pred_kernel<<<(int)((threads + 255) / 256), 256>>>(
            keypoints, timesteps, hand_tokens, head_w, head_b);
    }

    // Phase 2: XPBD Jacobi iterations (scatter with packed v4 REDs)
    int cur = 0;
    for (int it = 0; it < XPBD_ITERS_I; it++) {
        int nxt = cur ^ 1;
        if (it > 0) {
            cudaMemcpyAsync(x_base + (size_t)nxt * XN,
                            x_base + (size_t)cur * XN, XN * sizeof(float),
                            cudaMemcpyDeviceToDevice);
        }
        edge_kernel<<<(EE + 255) / 256, 256>>>(edge_index, rest, cur, nxt);
        cur = nxt;
    }

    // Phase 3: effective velocity
    final_kernel<<<(rows + 255) / 256, 256>>>(keypoints, timesteps, out, cur);
}